// round 4
// baseline (speedup 1.0000x reference)
#include <cuda_runtime.h>

// Persistent LSTM: B=128, T=365, D=32, H=512, fp32, out[b,t,:]=h_t.
// 128 CTAs x 512 threads. CTA tile = 32 batch x 16 units (x4 gates).
// W resident in smem (139 KB, [k][u] float4 = (wi,wf,wg,wo)); A tile
// (h|x, pitch 548) staged via cp.async each step. Lane tile 1m x 1u:
// per 4k: 1 LDS.128(a) + 4 LDS.128(w, full 128B wavefronts) + 8 FFMA2.
// Gate pairs (i,f),(g,o) in packed fma.rn.f32x2. 4x32-CTA group barrier.

#define B_   128
#define T_   365
#define D_   32
#define H_   512
#define G4   2048
#define KTOT 544
#define NCTA 128
#define NTHR 512
#define UPB  16
#define MPB  32
#define APITCH 548                                  // mult of 4, mod 32 = 4

#define SW_FLOATS (KTOT * UPB * 4)                  // 34816 floats = 139264 B
#define SMEM_BYTES (SW_FLOATS * 4 + MPB * APITCH * 4)  // 139264+70144=209408

__device__ unsigned int g_arrive[4];
__device__ volatile unsigned int g_release[4];

__global__ void init_barrier_kernel() {
    if (threadIdx.x < 4) { g_arrive[threadIdx.x] = 0u; g_release[threadIdx.x] = 0u; }
}

__device__ __forceinline__ unsigned long long pack2(float v) {
    unsigned long long r;
    asm("mov.b64 %0, {%1, %1};" : "=l"(r) : "f"(v));
    return r;
}
__device__ __forceinline__ void ffma2(unsigned long long& d,
                                      unsigned long long a,
                                      unsigned long long b) {
    asm("fma.rn.f32x2 %0, %1, %2, %0;" : "+l"(d) : "l"(a), "l"(b));
}
__device__ __forceinline__ void unpack2(unsigned long long v, float& lo, float& hi) {
    asm("mov.b64 {%0, %1}, %2;" : "=f"(lo), "=f"(hi) : "l"(v));
}
__device__ __forceinline__ float fsig(float z) {
    return 1.0f / (1.0f + __expf(-z));
}
__device__ __forceinline__ float ftanh_(float z) {
    return 1.0f - 2.0f / (__expf(2.0f * z) + 1.0f);
}
__device__ __forceinline__ void cp_async16(unsigned int smem_dst, const void* gsrc) {
    asm volatile("cp.async.cg.shared.global [%0], [%1], 16;"
                 :: "r"(smem_dst), "l"(gsrc) : "memory");
}
__device__ __forceinline__ void cp_async_wait_all() {
    asm volatile("cp.async.commit_group;\n\tcp.async.wait_group 0;" ::: "memory");
}
__device__ __forceinline__ unsigned int smem_u32(const void* p) {
    return (unsigned int)__cvta_generic_to_shared(p);
}

__global__ __launch_bounds__(NTHR, 1) void lstm_persistent(
    const float* __restrict__ x,    // [B,T,D]
    const float* __restrict__ Wx,   // [D,4H]
    const float* __restrict__ Wh,   // [H,4H]
    const float* __restrict__ bias, // [4H]
    float* __restrict__ out)        // [B,T,H]
{
    extern __shared__ float smem[];
    float* sWf = smem;                      // [KTOT][UPB] float4 (wi,wf,wg,wo)
    float* sA  = smem + SW_FLOATS;          // [MPB][APITCH]

    const int tid  = threadIdx.x;
    const int warp = tid >> 5;
    const int lane = tid & 31;
    const int wm   = warp & 7;              // m-block of 4 rows
    const int wu   = warp >> 3;             // u-half
    const int mi   = lane >> 3;
    const int ui   = lane & 7;
    const int ub   = blockIdx.x & 31;
    const int mb   = blockIdx.x >> 5;       // barrier group
    const int j0   = ub * UPB;
    const int m0   = mb * MPB;
    const int m    = wm * 4 + mi;           // 0..31
    const int u    = wu * 8 + ui;           // 0..15
    const int j    = j0 + u;
    const int mrow = m0 + m;

    // ---- prologue: stage W slice, gate-interleaved [k][u] = (wi,wf,wg,wo) ----
    for (int idx = tid; idx < KTOT * UPB; idx += NTHR) {
        int k  = idx >> 4;
        int uu = idx & 15;
        int col = j0 + uu;
        const float* Wrow = (k < H_) ? (Wh + (size_t)k * G4)
                                     : (Wx + (size_t)(k - H_) * G4);
        float4 w = make_float4(Wrow[col], Wrow[H_ + col],
                               Wrow[2 * H_ + col], Wrow[3 * H_ + col]);
        *(float4*)(sWf + (size_t)(k * UPB + uu) * 4) = w;
    }
    const float bi = bias[j];
    const float bf = bias[H_ + j];
    const float bg = bias[2 * H_ + j];
    const float bo = bias[3 * H_ + j];
    float c_reg = 0.f;
    __syncthreads();

    const ulonglong2* sW2 = (const ulonglong2*)sWf;   // [k*16 + u]
    const float* aRow = sA + m * APITCH;

    for (int t = 0; t < T_; ++t) {
        // ---- stage A tile: h (cols 0..511) + x (cols 512..543) ----
        {
            // h-part: thread (mr = tid>>4, qi = tid&15) does 8 float4s
            int mr = tid >> 4, qi = tid & 15;
            float* dstRow = sA + mr * APITCH;
            if (t == 0) {
                #pragma unroll
                for (int i = 0; i < 8; ++i) {
                    int q = qi + i * 16;
                    *(float4*)(dstRow + q * 4) = make_float4(0.f, 0.f, 0.f, 0.f);
                }
            } else {
                const float* srcRow = out + (size_t)(m0 + mr) * ((size_t)T_ * H_)
                                          + (size_t)(t - 1) * H_;
                #pragma unroll
                for (int i = 0; i < 8; ++i) {
                    int q = qi + i * 16;
                    cp_async16(smem_u32(dstRow + q * 4), srcRow + q * 4);
                }
            }
            // x-part: 256 float4s by threads 0..255
            if (tid < 256) {
                int r = tid >> 3, q = tid & 7;
                cp_async16(smem_u32(sA + r * APITCH + 512 + q * 4),
                           x + (size_t)(m0 + r) * (T_ * D_) + t * D_ + q * 4);
            }
            cp_async_wait_all();
        }
        __syncthreads();

        // ---- z = [h,x] @ W : 1 m-row x 1 unit x 4 gates per lane ----
        unsigned long long acc_if = 0, acc_go = 0;
        #pragma unroll 4
        for (int k4 = 0; k4 < KTOT; k4 += 4) {
            float4 a4 = *(const float4*)(aRow + k4);
            ulonglong2 w0 = sW2[(k4 + 0) * UPB + u];
            ulonglong2 w1 = sW2[(k4 + 1) * UPB + u];
            ulonglong2 w2 = sW2[(k4 + 2) * UPB + u];
            ulonglong2 w3 = sW2[(k4 + 3) * UPB + u];
            unsigned long long a0 = pack2(a4.x), a1 = pack2(a4.y);
            unsigned long long a2 = pack2(a4.z), a3 = pack2(a4.w);
            ffma2(acc_if, a0, w0.x); ffma2(acc_go, a0, w0.y);
            ffma2(acc_if, a1, w1.x); ffma2(acc_go, a1, w1.y);
            ffma2(acc_if, a2, w2.x); ffma2(acc_go, a2, w2.y);
            ffma2(acc_if, a3, w3.x); ffma2(acc_go, a3, w3.y);
        }

        // ---- gates, state, writeback ----
        float zi, zf, zg, zo;
        unpack2(acc_if, zi, zf);
        unpack2(acc_go, zg, zo);
        float ig = fsig(zi + bi);
        float fg = fsig(zf + bf);
        float gg = ftanh_(zg + bg);
        float og = fsig(zo + bo);
        float cn = fg * c_reg + ig * gg;
        c_reg = cn;
        out[(size_t)mrow * ((size_t)T_ * H_) + (size_t)t * H_ + j] =
            og * ftanh_(cn);

        // ---- group barrier (32 CTAs sharing this m-block) ----
        __threadfence();
        __syncthreads();
        if (tid == 0) {
            unsigned prev = atomicAdd(&g_arrive[mb], 1u);
            if (prev == (unsigned)(t + 1) * 32u - 1u) {
                g_release[mb] = (unsigned)(t + 1);
            } else {
                while (g_release[mb] < (unsigned)(t + 1)) { }
            }
        }
        __syncthreads();
    }
}

extern "C" void kernel_launch(void* const* d_in, const int* in_sizes, int n_in,
                              void* d_out, int out_size) {
    const float* x  = (const float*)d_in[0];
    const float* Wx = (const float*)d_in[1];
    const float* Wh = (const float*)d_in[2];
    const float* b  = (const float*)d_in[3];
    float* out = (float*)d_out;

    static bool attr_set = false;
    if (!attr_set) {
        cudaFuncSetAttribute(lstm_persistent,
                             cudaFuncAttributeMaxDynamicSharedMemorySize,
                             SMEM_BYTES);
        attr_set = true;
    }

    init_barrier_kernel<<<1, 32>>>();
    lstm_persistent<<<NCTA, NTHR, SMEM_BYTES>>>(x, Wx, Wh, b, out);
}

// round 5
// speedup vs baseline: 1.7979x; 1.7979x over previous
#include <cuda_runtime.h>

// Persistent LSTM: B=128, T=365, D=32, H=512, fp32, out[b,t,:]=h_t.
// 128 CTAs x 128 threads (4 warps). CTA tile: 32 batch-rows x 16 units.
// W resident in smem TRANSPOSED: sWT[gatecol][k], gatecol = gate*16+u,
// pitch 548 (conflict-free distinct LDS.128: lane owns rows lane, lane+32).
// A tile TRANSPOSED: sAT[k][m] (m contiguous, pitch 36) -> m-pair operand is
// one uniform LDS.128 (2 f32x2, no packing). Lane l holds gates {l>>4, l>>4+2}
// of unit l&15; epilogue fuses partners via shfl.xor(16); c-state in lanes>=16.
// h written to out AND to transposed aux g_hT so next step stages via cp.async.

#define B_   128
#define T_   365
#define D_   32
#define H_   512
#define G4   2048
#define KTOT 544
#define NCTA 128
#define NTHR 128
#define WPITCH 548              // floats; 548 % 32 == 4 -> conflict-free
#define APITCH 36               // floats; 144B rows, 16B aligned

#define SW_FLOATS (64 * WPITCH)                      // 35072
#define SA_FLOATS (KTOT * APITCH)                    // 19584
#define SMEM_BYTES ((SW_FLOATS + SA_FLOATS) * 4)     // 218624 B

__device__ float g_hT[2][4][512][32];   // [parity][m-group][unit][m-local]
__device__ unsigned int g_arrive[4];
__device__ volatile unsigned int g_release[4];

__global__ void init_barrier_kernel() {
    if (threadIdx.x < 4) { g_arrive[threadIdx.x] = 0u; g_release[threadIdx.x] = 0u; }
}

__device__ __forceinline__ unsigned long long pack2(float v) {
    unsigned long long r;
    asm("mov.b64 %0, {%1, %1};" : "=l"(r) : "f"(v));
    return r;
}
__device__ __forceinline__ void ffma2(unsigned long long& d,
                                      unsigned long long a,
                                      unsigned long long b) {
    asm("fma.rn.f32x2 %0, %1, %2, %0;" : "+l"(d) : "l"(a), "l"(b));
}
__device__ __forceinline__ void unpack2(unsigned long long v, float& lo, float& hi) {
    asm("mov.b64 {%0, %1}, %2;" : "=f"(lo), "=f"(hi) : "l"(v));
}
__device__ __forceinline__ float fsig(float z) {
    return 1.0f / (1.0f + __expf(-z));
}
__device__ __forceinline__ float ftanh_(float z) {
    return 1.0f - 2.0f / (__expf(2.0f * z) + 1.0f);
}
__device__ __forceinline__ void cp_async16(unsigned int smem_dst, const void* gsrc) {
    asm volatile("cp.async.cg.shared.global [%0], [%1], 16;"
                 :: "r"(smem_dst), "l"(gsrc) : "memory");
}
__device__ __forceinline__ void cp_async_wait_all() {
    asm volatile("cp.async.commit_group;\n\tcp.async.wait_group 0;" ::: "memory");
}
__device__ __forceinline__ unsigned int smem_u32(const void* p) {
    return (unsigned int)__cvta_generic_to_shared(p);
}

__global__ __launch_bounds__(NTHR, 1) void lstm_persistent(
    const float* __restrict__ x,    // [B,T,D]
    const float* __restrict__ Wx,   // [D,4H]
    const float* __restrict__ Wh,   // [H,4H]
    const float* __restrict__ bias, // [4H]
    float* __restrict__ out)        // [B,T,H]
{
    extern __shared__ float smem[];
    float* sWT = smem;                         // [64][WPITCH]
    float* sAT = smem + SW_FLOATS;             // [KTOT][APITCH]

    const int tid  = threadIdx.x;
    const int warp = tid >> 5;                 // 0..3 : owns m-rows 8w..8w+7
    const int lane = tid & 31;
    const int ub   = blockIdx.x & 31;
    const int mb   = blockIdx.x >> 5;          // barrier / m group
    const int j0   = ub * 16;
    const int m0   = mb * 32;
    const int u    = lane & 15;
    const int gA   = lane >> 4;                // gate 0 or 1 (i / f)
    const int j    = j0 + u;

    // ---- prologue: stage W transposed: sWT[r][k], r = g*16+u ----
    for (int i = 0; i < (64 * KTOT) / NTHR; ++i) {     // 272 iters
        int idx = i * NTHR + tid;
        int r = idx & 63;
        int k = idx >> 6;
        int col = (r >> 4) * H_ + j0 + (r & 15);
        float v = (k < H_) ? Wh[(size_t)k * G4 + col]
                           : Wx[(size_t)(k - H_) * G4 + col];
        sWT[r * WPITCH + k] = v;
    }
    const float biasA = bias[gA * H_ + j];          // i (lanes<16) / f (>=16)
    const float biasB = bias[(gA + 2) * H_ + j];    // g (lanes<16) / o (>=16)
    float c_reg[8] = {0.f,0.f,0.f,0.f,0.f,0.f,0.f,0.f};  // lanes>=16 only
    __syncthreads();

    const float* wrowA = sWT + lane * WPITCH;
    const float* wrowB = sWT + (lane + 32) * WPITCH;
    const float* aBase = sAT + warp * 8;            // uniform per warp

    for (int t = 0; t < T_; ++t) {
        // ---- stage x part: sAT[512+d][m] (transposed via LDG+STS) ----
        {
            int d = tid & 31;
            int mb4 = tid >> 5;
            #pragma unroll
            for (int rr = 0; rr < 8; ++rr) {
                int m = mb4 + rr * 4;
                sAT[(512 + d) * APITCH + m] =
                    x[(size_t)(m0 + m) * (T_ * D_) + (size_t)t * D_ + d];
            }
        }
        // ---- stage h part: straight copy from g_hT (or zeros at t=0) ----
        if (t == 0) {
            float4 z4 = make_float4(0.f, 0.f, 0.f, 0.f);
            #pragma unroll
            for (int i = 0; i < 32; ++i) {
                int idx = i * NTHR + tid;            // 4096 16B chunks
                int k = idx >> 3, c = idx & 7;
                *(float4*)(sAT + k * APITCH + c * 4) = z4;
            }
        } else {
            const float* hsrc = &g_hT[(t - 1) & 1][mb][0][0];   // [512][32]
            #pragma unroll
            for (int i = 0; i < 32; ++i) {
                int idx = i * NTHR + tid;
                int k = idx >> 3, c = idx & 7;
                cp_async16(smem_u32(sAT + k * APITCH + c * 4),
                           hsrc + k * 32 + c * 4);
            }
            cp_async_wait_all();
        }
        __syncthreads();

        // ---- k-loop: per lane, 8 m x 2 gate-cols ----
        unsigned long long acc[4][2] = {};
        #pragma unroll 2
        for (int k4 = 0; k4 < KTOT; k4 += 4) {
            float4 wa = *(const float4*)(wrowA + k4);    // distinct 128B/wf
            float4 wb = *(const float4*)(wrowB + k4);
            #pragma unroll
            for (int kk = 0; kk < 4; ++kk) {
                const float* arow = aBase + (k4 + kk) * APITCH;
                ulonglong2 a01 = *(const ulonglong2*)(arow);      // m-pairs 0,1
                ulonglong2 a23 = *(const ulonglong2*)(arow + 4);  // m-pairs 2,3
                float wak = (kk == 0) ? wa.x : (kk == 1) ? wa.y
                          : (kk == 2) ? wa.z : wa.w;
                float wbk = (kk == 0) ? wb.x : (kk == 1) ? wb.y
                          : (kk == 2) ? wb.z : wb.w;
                unsigned long long wa2 = pack2(wak);
                unsigned long long wb2 = pack2(wbk);
                ffma2(acc[0][0], a01.x, wa2); ffma2(acc[0][1], a01.x, wb2);
                ffma2(acc[1][0], a01.y, wa2); ffma2(acc[1][1], a01.y, wb2);
                ffma2(acc[2][0], a23.x, wa2); ffma2(acc[2][1], a23.x, wb2);
                ffma2(acc[3][0], a23.y, wa2); ffma2(acc[3][1], a23.y, wb2);
            }
        }

        // ---- epilogue: lanes<16 have (i,g); lanes>=16 have (f,o) ----
        float zA[8], zB[8];
        #pragma unroll
        for (int p = 0; p < 4; ++p) {
            unpack2(acc[p][0], zA[2 * p], zA[2 * p + 1]);
            unpack2(acc[p][1], zB[2 * p], zB[2 * p + 1]);
        }
        float v[8];
        if (lane < 16) {
            #pragma unroll
            for (int r = 0; r < 8; ++r)
                v[r] = fsig(zA[r] + biasA) * ftanh_(zB[r] + biasB);
        }
        #pragma unroll
        for (int r = 0; r < 8; ++r)
            v[r] = __shfl_sync(0xffffffffu, v[r], lane ^ 16);
        if (lane >= 16) {
            float* hdst = &g_hT[t & 1][mb][j][warp * 8];
            #pragma unroll
            for (int r = 0; r < 8; ++r) {
                float cn = fsig(zA[r] + biasA) * c_reg[r] + v[r];
                c_reg[r] = cn;
                float h = fsig(zB[r] + biasB) * ftanh_(cn);
                out[(size_t)(m0 + warp * 8 + r) * ((size_t)T_ * H_) +
                    (size_t)t * H_ + j] = h;
                hdst[r] = h;
            }
        }

        // ---- group barrier (32 CTAs sharing this m-group) ----
        __threadfence();
        __syncthreads();
        if (tid == 0) {
            unsigned prev = atomicAdd(&g_arrive[mb], 1u);
            if (prev == (unsigned)(t + 1) * 32u - 1u) {
                g_release[mb] = (unsigned)(t + 1);
            } else {
                while (g_release[mb] < (unsigned)(t + 1)) { }
            }
        }
        __syncthreads();
    }
}

extern "C" void kernel_launch(void* const* d_in, const int* in_sizes, int n_in,
                              void* d_out, int out_size) {
    const float* x  = (const float*)d_in[0];
    const float* Wx = (const float*)d_in[1];
    const float* Wh = (const float*)d_in[2];
    const float* b  = (const float*)d_in[3];
    float* out = (float*)d_out;

    static bool attr_set = false;
    if (!attr_set) {
        cudaFuncSetAttribute(lstm_persistent,
                             cudaFuncAttributeMaxDynamicSharedMemorySize,
                             SMEM_BYTES);
        attr_set = true;
    }

    init_barrier_kernel<<<1, 32>>>();
    lstm_persistent<<<NCTA, NTHR, SMEM_BYTES>>>(x, Wx, Wh, b, out);
}

// round 6
// speedup vs baseline: 1.8655x; 1.0376x over previous
#include <cuda_runtime.h>

// Persistent LSTM: B=128, T=365, D=32, H=512, fp32, out[b,t,:]=h_t.
// 128 CTAs x 256 threads (8 warps, 2/SMSP). CTA tile: 32 batch x 16 units.
// Split-K: warps 0-3 do k[0,272), warps 4-7 k[272,544); partials reduced in
// smem with add.rn.f32x2. W resident transposed sWT[gatecol][k] (pitch 548);
// A transposed sAT[k][m] (pitch 36). Lane l: gates {l>>4, (l>>4)+2} of unit
// l&15; epilogue pairs lanes via shfl.xor(16); c in lanes>=16 of warps 0-3.
// h -> out and transposed aux g_hT; 4x32-CTA group barrier per step.

#define B_   128
#define T_   365
#define D_   32
#define H_   512
#define G4   2048
#define KTOT 544
#define KSPL 272
#define NCTA 128
#define NTHR 256
#define WPITCH 548
#define APITCH 36

#define SW_FLOATS (64 * WPITCH)                  // 35072
#define SA_FLOATS (KTOT * APITCH)                // 19584
#define RED_U64   (128 * 9)                      // 128 entries, pitch 9 u64
#define SMEM_BYTES ((SW_FLOATS + SA_FLOATS) * 4 + RED_U64 * 8)   // 227840

__device__ float g_hT[2][4][512][32];   // [parity][m-group][unit][m-local]
__device__ unsigned int g_arrive[4];
__device__ volatile unsigned int g_release[4];

__global__ void init_barrier_kernel() {
    if (threadIdx.x < 4) { g_arrive[threadIdx.x] = 0u; g_release[threadIdx.x] = 0u; }
}

__device__ __forceinline__ unsigned long long pack2(float v) {
    unsigned long long r;
    asm("mov.b64 %0, {%1, %1};" : "=l"(r) : "f"(v));
    return r;
}
__device__ __forceinline__ void ffma2(unsigned long long& d,
                                      unsigned long long a,
                                      unsigned long long b) {
    asm("fma.rn.f32x2 %0, %1, %2, %0;" : "+l"(d) : "l"(a), "l"(b));
}
__device__ __forceinline__ void fadd2(unsigned long long& d, unsigned long long a) {
    asm("add.rn.f32x2 %0, %0, %1;" : "+l"(d) : "l"(a));
}
__device__ __forceinline__ void unpack2(unsigned long long v, float& lo, float& hi) {
    asm("mov.b64 {%0, %1}, %2;" : "=f"(lo), "=f"(hi) : "l"(v));
}
__device__ __forceinline__ float fsig(float z) {
    return 1.0f / (1.0f + __expf(-z));
}
__device__ __forceinline__ float ftanh_(float z) {
    return 1.0f - 2.0f / (__expf(2.0f * z) + 1.0f);
}
__device__ __forceinline__ void cp_async16(unsigned int smem_dst, const void* gsrc) {
    asm volatile("cp.async.cg.shared.global [%0], [%1], 16;"
                 :: "r"(smem_dst), "l"(gsrc) : "memory");
}
__device__ __forceinline__ void cp_async_wait_all() {
    asm volatile("cp.async.commit_group;\n\tcp.async.wait_group 0;" ::: "memory");
}
__device__ __forceinline__ unsigned int smem_u32(const void* p) {
    return (unsigned int)__cvta_generic_to_shared(p);
}

__global__ __launch_bounds__(NTHR, 1) void lstm_persistent(
    const float* __restrict__ x,    // [B,T,D]
    const float* __restrict__ Wx,   // [D,4H]
    const float* __restrict__ Wh,   // [H,4H]
    const float* __restrict__ bias, // [4H]
    float* __restrict__ out)        // [B,T,H]
{
    extern __shared__ float smem[];
    float* sWT = smem;                               // [64][WPITCH]
    float* sAT = smem + SW_FLOATS;                   // [KTOT][APITCH]
    unsigned long long* sRed =
        (unsigned long long*)(smem + SW_FLOATS + SA_FLOATS);  // [128][9]

    const int tid  = threadIdx.x;
    const int warp = tid >> 5;                 // 0..7
    const int lane = tid & 31;
    const int wm   = warp & 3;                 // m-group (rows 8wm..8wm+7)
    const int kh   = warp >> 2;                // k-half
    const int ub   = blockIdx.x & 31;
    const int mb   = blockIdx.x >> 5;
    const int j0   = ub * 16;
    const int m0   = mb * 32;
    const int u    = lane & 15;
    const int gA   = lane >> 4;
    const int j    = j0 + u;

    // ---- prologue: W transposed into smem: sWT[r][k], r = g*16+u ----
    for (int i = 0; i < (64 * KTOT) / NTHR; ++i) {   // 136 iters
        int idx = i * NTHR + tid;
        int r = idx & 63;
        int k = idx >> 6;
        int col = (r >> 4) * H_ + j0 + (r & 15);
        float v = (k < H_) ? Wh[(size_t)k * G4 + col]
                           : Wx[(size_t)(k - H_) * G4 + col];
        sWT[r * WPITCH + k] = v;
    }
    const float biasA = bias[gA * H_ + j];
    const float biasB = bias[(gA + 2) * H_ + j];
    float c_reg[8] = {0.f,0.f,0.f,0.f,0.f,0.f,0.f,0.f};
    __syncthreads();

    const float* wrowA = sWT + lane * WPITCH + kh * KSPL;
    const float* wrowB = sWT + (lane + 32) * WPITCH + kh * KSPL;
    const float* aBase = sAT + (size_t)kh * KSPL * APITCH + wm * 8;

    for (int t = 0; t < T_; ++t) {
        // ---- stage x rows: sAT[512+d][m] ----
        {
            int d  = tid & 31;
            int mg = tid >> 5;                       // 0..7
            #pragma unroll
            for (int rr = 0; rr < 4; ++rr) {
                int m = mg + rr * 8;
                sAT[(512 + d) * APITCH + m] =
                    x[(size_t)(m0 + m) * (T_ * D_) + (size_t)t * D_ + d];
            }
        }
        // ---- stage h rows (transposed aux buffer, straight copy) ----
        if (t == 0) {
            float4 z4 = make_float4(0.f, 0.f, 0.f, 0.f);
            #pragma unroll
            for (int i = 0; i < 16; ++i) {
                int idx = i * NTHR + tid;            // 4096 16B chunks
                int k = idx >> 3, c = idx & 7;
                *(float4*)(sAT + k * APITCH + c * 4) = z4;
            }
        } else {
            const float* hsrc = &g_hT[(t - 1) & 1][mb][0][0];   // [512][32]
            #pragma unroll
            for (int i = 0; i < 16; ++i) {
                int idx = i * NTHR + tid;
                int k = idx >> 3, c = idx & 7;
                cp_async16(smem_u32(sAT + k * APITCH + c * 4),
                           hsrc + k * 32 + c * 4);
            }
            cp_async_wait_all();
        }
        __syncthreads();

        // ---- k-loop (half range): 8 m x 2 gate-cols per lane ----
        unsigned long long acc[4][2] = {};
        #pragma unroll 2
        for (int k4 = 0; k4 < KSPL; k4 += 4) {
            float4 wa = *(const float4*)(wrowA + k4);
            float4 wb = *(const float4*)(wrowB + k4);
            #pragma unroll
            for (int kk = 0; kk < 4; ++kk) {
                const float* arow = aBase + (k4 + kk) * APITCH;
                ulonglong2 a01 = *(const ulonglong2*)(arow);
                ulonglong2 a23 = *(const ulonglong2*)(arow + 4);
                float wak = (kk == 0) ? wa.x : (kk == 1) ? wa.y
                          : (kk == 2) ? wa.z : wa.w;
                float wbk = (kk == 0) ? wb.x : (kk == 1) ? wb.y
                          : (kk == 2) ? wb.z : wb.w;
                unsigned long long wa2 = pack2(wak);
                unsigned long long wb2 = pack2(wbk);
                ffma2(acc[0][0], a01.x, wa2); ffma2(acc[0][1], a01.x, wb2);
                ffma2(acc[1][0], a01.y, wa2); ffma2(acc[1][1], a01.y, wb2);
                ffma2(acc[2][0], a23.x, wa2); ffma2(acc[2][1], a23.x, wb2);
                ffma2(acc[3][0], a23.y, wa2); ffma2(acc[3][1], a23.y, wb2);
            }
        }

        // ---- split-K reduction through smem ----
        if (kh == 1) {
            unsigned long long* dst = sRed + (size_t)(wm * 32 + lane) * 9;
            #pragma unroll
            for (int p = 0; p < 4; ++p) {
                dst[2 * p]     = acc[p][0];
                dst[2 * p + 1] = acc[p][1];
            }
        }
        __syncthreads();

        if (kh == 0) {
            const unsigned long long* src = sRed + (size_t)(wm * 32 + lane) * 9;
            #pragma unroll
            for (int p = 0; p < 4; ++p) {
                fadd2(acc[p][0], src[2 * p]);
                fadd2(acc[p][1], src[2 * p + 1]);
            }

            // ---- epilogue: lanes<16 (i,g); lanes>=16 (f,o) ----
            float zA[8], zB[8];
            #pragma unroll
            for (int p = 0; p < 4; ++p) {
                unpack2(acc[p][0], zA[2 * p], zA[2 * p + 1]);
                unpack2(acc[p][1], zB[2 * p], zB[2 * p + 1]);
            }
            float v[8];
            if (lane < 16) {
                #pragma unroll
                for (int r = 0; r < 8; ++r)
                    v[r] = fsig(zA[r] + biasA) * ftanh_(zB[r] + biasB);
            }
            #pragma unroll
            for (int r = 0; r < 8; ++r)
                v[r] = __shfl_sync(0xffffffffu, v[r], lane ^ 16);
            if (lane >= 16) {
                float* hdst = &g_hT[t & 1][mb][j][wm * 8];
                #pragma unroll
                for (int r = 0; r < 8; ++r) {
                    float cn = fsig(zA[r] + biasA) * c_reg[r] + v[r];
                    c_reg[r] = cn;
                    float h = fsig(zB[r] + biasB) * ftanh_(cn);
                    out[(size_t)(m0 + wm * 8 + r) * ((size_t)T_ * H_) +
                        (size_t)t * H_ + j] = h;
                    hdst[r] = h;
                }
            }
        }

        // ---- group barrier (32 CTAs sharing this m-group) ----
        __threadfence();
        __syncthreads();
        if (tid == 0) {
            unsigned prev = atomicAdd(&g_arrive[mb], 1u);
            if (prev == (unsigned)(t + 1) * 32u - 1u) {
                g_release[mb] = (unsigned)(t + 1);
            } else {
                while (g_release[mb] < (unsigned)(t + 1)) { }
            }
        }
        __syncthreads();
    }
}

extern "C" void kernel_launch(void* const* d_in, const int* in_sizes, int n_in,
                              void* d_out, int out_size) {
    const float* x  = (const float*)d_in[0];
    const float* Wx = (const float*)d_in[1];
    const float* Wh = (const float*)d_in[2];
    const float* b  = (const float*)d_in[3];
    float* out = (float*)d_out;

    static bool attr_set = false;
    if (!attr_set) {
        cudaFuncSetAttribute(lstm_persistent,
                             cudaFuncAttributeMaxDynamicSharedMemorySize,
                             SMEM_BYTES);
        attr_set = true;
    }

    init_barrier_kernel<<<1, 32>>>();
    lstm_persistent<<<NCTA, NTHR, SMEM_BYTES>>>(x, Wx, Wh, b, out);
}